// round 15
// baseline (speedup 1.0000x reference)
#include <cuda_runtime.h>
#include <cuda_fp16.h>

// rate_RNN_mante: T=1000 sequential steps, B=64, IN=4, H=512, OUT=3.
// Wr = (l*pin) @ pout^T is rank-2 -> two H-wide reductions (s0,s1) per step.
//
// Scan (R13 structure): one CTA/batch, 4 warps x 32 lanes x 4 units. Loop =
// 2 chain FMAs, MUFU.TANH, po-products, 4 shfl rounds, STS 8 partials,
// __syncthreads, 4 broadcast LDS.128 + scalar tree. r exported as fp16
// (2x cvt.f16x2 + STG.64) inside the shuffle-latency shadow.
// Project: y = Wout @ r, one warp/row; r read as uint4 (8 halves / LDG.128),
// weights as float4 LDS.128 (R12's regression was SCALAR weight loads).
// Traffic 131->65.5 MB, and 65.5 MB fits in L2 (126 MB) for extra BW.

#define TSTEPS 1000
#define BATCH  64
#define HID    512
#define OUTDIM 3
#define NTHR   128          // 4 warps
#define UPT    4            // hidden units per thread
#define NROWS  (TSTEPS * BATCH)

// fp16 r scratch: [row][512 halves] as uint2 (4 halves) -> 65.5 MB
__device__ uint2 g_rh[NROWS * (HID / 4)];

__global__ __launch_bounds__(NTHR, 1)
void rate_rnn_scan_kernel(const float* __restrict__ x,
                          const float* __restrict__ Win,
                          const float* __restrict__ pin,
                          const float* __restrict__ pout,
                          const float* __restrict__ l)
{
    const int b    = blockIdx.x;
    const int tid  = threadIdx.x;
    const int lane = tid & 31;
    const int wid  = tid >> 5;
    const int half = lane >> 4;            // 0: lanes 0-15, 1: lanes 16-31
    const int slot = wid * 2 + half;       // 8 partial slots
    const bool writer = ((lane & 15) == 0);

    __shared__ float4 xs[TSTEPS + 1];             // staged input (+1 pad)
    __shared__ __align__(16) float2 sp[2][8];     // double-buffered s partials

    const float4* x4 = reinterpret_cast<const float4*>(x);  // x: [T,B,4,1]
    for (int t = tid; t < TSTEPS; t += NTHR)
        xs[t] = x4[t * BATCH + b];
    if (tid == 0) xs[TSTEPS] = make_float4(0.f, 0.f, 0.f, 0.f);

    const float lm = 0.90483741803595952735f;   // exp(-dt/taum) = exp(-0.1)
    const float om = 1.0f - lm;
    const float l0 = l[0], l1 = l[1];

    float4 wi[UPT];
    float  pi0[UPT], pi1[UPT], po0[UPT], po1[UPT];
    float  acc[UPT], M[UPT];
#pragma unroll
    for (int k = 0; k < UPT; ++k) {
        int h = tid * UPT + k;
        float4 w = reinterpret_cast<const float4*>(Win)[h];
        wi[k] = make_float4(w.x * om, w.y * om, w.z * om, w.w * om);
        pi0[k] = pin[h * 2 + 0] * l0 * om;
        pi1[k] = pin[h * 2 + 1] * l1 * om;
        po0[k] = pout[h * 2 + 0];
        po1[k] = pout[h * 2 + 1];
        M[k]   = 0.0f;
    }

    float s0 = 0.f, s1 = 0.f;       // pout^T tanh(mem_{t-1}); zero at t=0
    int buf = 0;
    uint2* rrow = g_rh + (size_t)b * (HID / 4) + tid;

    __syncthreads();   // xs staged

    {   // prologue: acc for t=0 (M = 0)
        float4 x0 = xs[0];
#pragma unroll
        for (int k = 0; k < UPT; ++k)
            acc[k] = fmaf(wi[k].w, x0.w, fmaf(wi[k].z, x0.z,
                     fmaf(wi[k].y, x0.y, wi[k].x * x0.x)));
    }

    for (int t = 0; t < TSTEPS; ++t) {
        // ---- critical chain: s -> M -> tanh (single MUFU.TANH) ----
        float r[UPT];
#pragma unroll
        for (int k = 0; k < UPT; ++k) {
            float m = fmaf(pi1[k], s1, fmaf(pi0[k], s0, acc[k]));
            M[k] = m;
            asm("tanh.approx.f32 %0, %1;" : "=f"(r[k]) : "f"(m));
        }

        // s-products + 4 shuffle rounds (only pre-barrier reduction work)
        float v = fmaf(po0[1], r[1], po0[0] * r[0]) + fmaf(po0[3], r[3], po0[2] * r[2]);
        float u = fmaf(po1[1], r[1], po1[0] * r[0]) + fmaf(po1[3], r[3], po1[2] * r[2]);
#pragma unroll
        for (int off = 1; off <= 8; off <<= 1) {
            v += __shfl_down_sync(0xffffffffu, v, off);
            u += __shfl_down_sync(0xffffffffu, u, off);
        }

        // shuffle-shadow work: fp16 r export + next-step acc
        {
            union { __half2 h[2]; uint2 q; } pk;
            pk.h[0] = __floats2half2_rn(r[0], r[1]);
            pk.h[1] = __floats2half2_rn(r[2], r[3]);
            rrow[(size_t)t * (BATCH * (HID / 4))] = pk.q;
        }
        float4 xtn = xs[t + 1];
#pragma unroll
        for (int k = 0; k < UPT; ++k) {
            float iin = fmaf(wi[k].w, xtn.w, fmaf(wi[k].z, xtn.z,
                        fmaf(wi[k].y, xtn.y, wi[k].x * xtn.x)));
            acc[k] = fmaf(lm, M[k], iin);
        }

        if (writer) sp[buf][slot] = make_float2(v, u);
        __syncthreads();   // 4-warp barrier

        // 8 s-partials as 4 broadcast float4 loads + depth-3 tree
        const float4* q = reinterpret_cast<const float4*>(sp[buf]);
        float4 q0 = q[0], q1 = q[1], q2 = q[2], q3 = q[3];
        s0 = ((q0.x + q0.z) + (q1.x + q1.z)) + ((q2.x + q2.z) + (q3.x + q3.z));
        s1 = ((q0.y + q0.w) + (q1.y + q1.w)) + ((q2.y + q2.w) + (q3.y + q3.w));
        buf ^= 1;
    }
}

// y[row,o] = sum_h Wout[o,h]*r[row,h]; one warp per row, fp16 r.
// All weight reads are vectorized LDS.128; r reads are LDG.128 (8 halves).
__global__ __launch_bounds__(256, 4)
void project_y_kernel(const float* __restrict__ Wout, float* __restrict__ out)
{
    __shared__ __align__(16) float ws[OUTDIM * HID];   // 6 KB
    const int tid  = threadIdx.x;
    const int lane = tid & 31;
    const int wrp  = tid >> 5;

    for (int i = tid; i < OUTDIM * HID; i += 256)
        ws[i] = Wout[i];
    __syncthreads();

    const float4* ws4 = reinterpret_cast<const float4*>(ws);
    int row = blockIdx.x * 8 + wrp;                    // [0, 64000)
    const uint4* rp = reinterpret_cast<const uint4*>(g_rh) + (size_t)row * (HID / 8);

    float y0 = 0.f, y1 = 0.f, y2 = 0.f;
#pragma unroll
    for (int j = 0; j < 2; ++j) {
        int m = lane * 2 + j;                          // uint4 idx: halves [8m, 8m+8)
        uint4 rv = rp[m];
        const __half2* hp = reinterpret_cast<const __half2*>(&rv);
        float2 f0 = __half22float2(hp[0]);
        float2 f1 = __half22float2(hp[1]);
        float2 f2 = __half22float2(hp[2]);
        float2 f3 = __half22float2(hp[3]);

        // per output: two float4 weight vectors cover the 8 halves
#pragma unroll
        for (int o = 0; o < OUTDIM; ++o) {
            float4 a = ws4[o * (HID / 4) + 2 * m];
            float4 c = ws4[o * (HID / 4) + 2 * m + 1];
            float acc =        fmaf(a.x, f0.x, a.y * f0.y);
            acc = fmaf(a.z, f1.x, fmaf(a.w, f1.y, acc));
            acc = fmaf(c.x, f2.x, fmaf(c.y, f2.y, acc));
            acc = fmaf(c.z, f3.x, fmaf(c.w, f3.y, acc));
            if (o == 0) y0 += acc; else if (o == 1) y1 += acc; else y2 += acc;
        }
    }
#pragma unroll
    for (int off = 16; off >= 1; off >>= 1) {
        y0 += __shfl_xor_sync(0xffffffffu, y0, off);
        y1 += __shfl_xor_sync(0xffffffffu, y1, off);
        y2 += __shfl_xor_sync(0xffffffffu, y2, off);
    }
    if (lane == 0) {
        out[row * OUTDIM + 0] = y0;   // y: [T,B,OUT,1], row = t*B + b
        out[row * OUTDIM + 1] = y1;
        out[row * OUTDIM + 2] = y2;
    }
}

extern "C" void kernel_launch(void* const* d_in, const int* in_sizes, int n_in,
                              void* d_out, int out_size)
{
    const float* x    = (const float*)d_in[0];  // [1000,64,4,1]
    const float* Win  = (const float*)d_in[1];  // [512,4]
    const float* Wout = (const float*)d_in[2];  // [3,512]
    const float* pin  = (const float*)d_in[3];  // [512,2]
    const float* pout = (const float*)d_in[4];  // [512,2]
    const float* l    = (const float*)d_in[5];  // [2]

    rate_rnn_scan_kernel<<<BATCH, NTHR>>>(x, Win, pin, pout, l);
    project_y_kernel<<<NROWS / 8, 256>>>(Wout, (float*)d_out);
}

// round 16
// speedup vs baseline: 1.1879x; 1.1879x over previous
#include <cuda_runtime.h>
#include <cuda_fp16.h>

// rate_RNN_mante: T=1000 sequential steps, B=64, IN=4, H=512, OUT=3.
// Wr = (l*pin) @ pout^T is rank-2 -> two H-wide reductions (s0,s1) per step.
//
// Scan (unchanged from R13/R14, measured ~154us): one CTA/batch, 4 warps x
// 32 lanes x 4 units. Loop = 2 chain FMAs, MUFU.TANH, po-products, 4 shfl
// rounds, STS 8 partials, __syncthreads, 4 broadcast LDS.128 + tree.
// r exported fp16 (2x cvt.f16x2 + STG.64) in the shuffle shadow.
//
// Project (FIXED): y = Wout @ r, one warp/row. r read as rp[j*32+lane] --
// COALESCED uint4 (the R12/R14 regressions came from rp[lane*2+j]: 32B-stride
// lanes -> 50% sector use -> L1-wavefront-bound). Weights pre-reordered in
// smem (wsA/wsB per uint4 index) so LDS.128s are consecutive/conflict-free.

#define TSTEPS 1000
#define BATCH  64
#define HID    512
#define OUTDIM 3
#define NTHR   128          // 4 warps
#define UPT    4            // hidden units per thread
#define NROWS  (TSTEPS * BATCH)

// fp16 r scratch: [row][512 halves] as uint2 (4 halves) -> 65.5 MB
__device__ uint2 g_rh[NROWS * (HID / 4)];

__global__ __launch_bounds__(NTHR, 1)
void rate_rnn_scan_kernel(const float* __restrict__ x,
                          const float* __restrict__ Win,
                          const float* __restrict__ pin,
                          const float* __restrict__ pout,
                          const float* __restrict__ l)
{
    const int b    = blockIdx.x;
    const int tid  = threadIdx.x;
    const int lane = tid & 31;
    const int wid  = tid >> 5;
    const int half = lane >> 4;            // 0: lanes 0-15, 1: lanes 16-31
    const int slot = wid * 2 + half;       // 8 partial slots
    const bool writer = ((lane & 15) == 0);

    __shared__ float4 xs[TSTEPS + 1];             // staged input (+1 pad)
    __shared__ __align__(16) float2 sp[2][8];     // double-buffered s partials

    const float4* x4 = reinterpret_cast<const float4*>(x);  // x: [T,B,4,1]
    for (int t = tid; t < TSTEPS; t += NTHR)
        xs[t] = x4[t * BATCH + b];
    if (tid == 0) xs[TSTEPS] = make_float4(0.f, 0.f, 0.f, 0.f);

    const float lm = 0.90483741803595952735f;   // exp(-dt/taum) = exp(-0.1)
    const float om = 1.0f - lm;
    const float l0 = l[0], l1 = l[1];

    float4 wi[UPT];
    float  pi0[UPT], pi1[UPT], po0[UPT], po1[UPT];
    float  acc[UPT], M[UPT];
#pragma unroll
    for (int k = 0; k < UPT; ++k) {
        int h = tid * UPT + k;
        float4 w = reinterpret_cast<const float4*>(Win)[h];
        wi[k] = make_float4(w.x * om, w.y * om, w.z * om, w.w * om);
        pi0[k] = pin[h * 2 + 0] * l0 * om;
        pi1[k] = pin[h * 2 + 1] * l1 * om;
        po0[k] = pout[h * 2 + 0];
        po1[k] = pout[h * 2 + 1];
        M[k]   = 0.0f;
    }

    float s0 = 0.f, s1 = 0.f;       // pout^T tanh(mem_{t-1}); zero at t=0
    int buf = 0;
    uint2* rrow = g_rh + (size_t)b * (HID / 4) + tid;

    __syncthreads();   // xs staged

    {   // prologue: acc for t=0 (M = 0)
        float4 x0 = xs[0];
#pragma unroll
        for (int k = 0; k < UPT; ++k)
            acc[k] = fmaf(wi[k].w, x0.w, fmaf(wi[k].z, x0.z,
                     fmaf(wi[k].y, x0.y, wi[k].x * x0.x)));
    }

    for (int t = 0; t < TSTEPS; ++t) {
        // ---- critical chain: s -> M -> tanh (single MUFU.TANH) ----
        float r[UPT];
#pragma unroll
        for (int k = 0; k < UPT; ++k) {
            float m = fmaf(pi1[k], s1, fmaf(pi0[k], s0, acc[k]));
            M[k] = m;
            asm("tanh.approx.f32 %0, %1;" : "=f"(r[k]) : "f"(m));
        }

        // s-products + 4 shuffle rounds (only pre-barrier reduction work)
        float v = fmaf(po0[1], r[1], po0[0] * r[0]) + fmaf(po0[3], r[3], po0[2] * r[2]);
        float u = fmaf(po1[1], r[1], po1[0] * r[0]) + fmaf(po1[3], r[3], po1[2] * r[2]);
#pragma unroll
        for (int off = 1; off <= 8; off <<= 1) {
            v += __shfl_down_sync(0xffffffffu, v, off);
            u += __shfl_down_sync(0xffffffffu, u, off);
        }

        // shuffle-shadow work: fp16 r export + next-step acc
        {
            union { __half2 h[2]; uint2 q; } pk;
            pk.h[0] = __floats2half2_rn(r[0], r[1]);
            pk.h[1] = __floats2half2_rn(r[2], r[3]);
            rrow[(size_t)t * (BATCH * (HID / 4))] = pk.q;
        }
        float4 xtn = xs[t + 1];
#pragma unroll
        for (int k = 0; k < UPT; ++k) {
            float iin = fmaf(wi[k].w, xtn.w, fmaf(wi[k].z, xtn.z,
                        fmaf(wi[k].y, xtn.y, wi[k].x * xtn.x)));
            acc[k] = fmaf(lm, M[k], iin);
        }

        if (writer) sp[buf][slot] = make_float2(v, u);
        __syncthreads();   // 4-warp barrier

        // 8 s-partials as 4 broadcast float4 loads + depth-3 tree
        const float4* q = reinterpret_cast<const float4*>(sp[buf]);
        float4 q0 = q[0], q1 = q[1], q2 = q[2], q3 = q[3];
        s0 = ((q0.x + q0.z) + (q1.x + q1.z)) + ((q2.x + q2.z) + (q3.x + q3.z));
        s1 = ((q0.y + q0.w) + (q1.y + q1.w)) + ((q2.y + q2.w) + (q3.y + q3.w));
        buf ^= 1;
    }
}

// y[row,o] = sum_h Wout[o,h]*r[row,h]; one warp per row, fp16 r.
// r: rp[j*32+lane] -> coalesced LDG.128 (full 32B sectors).
// Weights: reordered smem arrays wsA/wsB indexed by uint4 index m, so
// lane m accesses are consecutive -> conflict-free LDS.128.
__global__ __launch_bounds__(256, 4)
void project_y_kernel(const float* __restrict__ Wout, float* __restrict__ out)
{
    __shared__ __align__(16) float4 wsA[OUTDIM * 64];   // 3 KB
    __shared__ __align__(16) float4 wsB[OUTDIM * 64];   // 3 KB
    const int tid  = threadIdx.x;
    const int lane = tid & 31;
    const int wrp  = tid >> 5;

    const float4* w4 = reinterpret_cast<const float4*>(Wout);
    for (int i = tid; i < OUTDIM * 64; i += 256) {
        int o = i >> 6, m = i & 63;
        wsA[i] = w4[o * (HID / 4) + 2 * m];       // halves [8m, 8m+4)
        wsB[i] = w4[o * (HID / 4) + 2 * m + 1];   // halves [8m+4, 8m+8)
    }
    __syncthreads();

    int row = blockIdx.x * 8 + wrp;                    // [0, 64000)
    const uint4* rp = reinterpret_cast<const uint4*>(g_rh) + (size_t)row * (HID / 8);

    float y0 = 0.f, y1 = 0.f, y2 = 0.f;
#pragma unroll
    for (int j = 0; j < 2; ++j) {
        int m = j * 32 + lane;                         // COALESCED uint4 index
        uint4 rv = rp[m];
        const __half2* hp = reinterpret_cast<const __half2*>(&rv);
        float2 f0 = __half22float2(hp[0]);
        float2 f1 = __half22float2(hp[1]);
        float2 f2 = __half22float2(hp[2]);
        float2 f3 = __half22float2(hp[3]);
#pragma unroll
        for (int o = 0; o < OUTDIM; ++o) {
            float4 a = wsA[o * 64 + m];                // conflict-free LDS.128
            float4 c = wsB[o * 64 + m];
            float acc =            fmaf(a.x, f0.x, a.y * f0.y);
            acc = fmaf(a.z, f1.x, fmaf(a.w, f1.y, acc));
            acc = fmaf(c.x, f2.x, fmaf(c.y, f2.y, acc));
            acc = fmaf(c.z, f3.x, fmaf(c.w, f3.y, acc));
            if (o == 0) y0 += acc; else if (o == 1) y1 += acc; else y2 += acc;
        }
    }
#pragma unroll
    for (int off = 16; off >= 1; off >>= 1) {
        y0 += __shfl_xor_sync(0xffffffffu, y0, off);
        y1 += __shfl_xor_sync(0xffffffffu, y1, off);
        y2 += __shfl_xor_sync(0xffffffffu, y2, off);
    }
    if (lane == 0) {
        out[row * OUTDIM + 0] = y0;   // y: [T,B,OUT,1], row = t*B + b
        out[row * OUTDIM + 1] = y1;
        out[row * OUTDIM + 2] = y2;
    }
}

extern "C" void kernel_launch(void* const* d_in, const int* in_sizes, int n_in,
                              void* d_out, int out_size)
{
    const float* x    = (const float*)d_in[0];  // [1000,64,4,1]
    const float* Win  = (const float*)d_in[1];  // [512,4]
    const float* Wout = (const float*)d_in[2];  // [3,512]
    const float* pin  = (const float*)d_in[3];  // [512,2]
    const float* pout = (const float*)d_in[4];  // [512,2]
    const float* l    = (const float*)d_in[5];  // [2]

    rate_rnn_scan_kernel<<<BATCH, NTHR>>>(x, Win, pin, pout, l);
    project_y_kernel<<<NROWS / 8, 256>>>(Wout, (float*)d_out);
}

// round 17
// speedup vs baseline: 1.2206x; 1.0275x over previous
#include <cuda_runtime.h>
#include <cuda_fp16.h>

// rate_RNN_mante: T=1000 sequential steps, B=64, IN=4, H=512, OUT=3.
// Wr = (l*pin) @ pout^T is rank-2 -> two H-wide reductions (s0,s1) per step.
//
// Scan (unchanged from R15, measured ~155us): one CTA/batch, 4 warps x
// 32 lanes x 4 units. Loop = 2 chain FMAs, MUFU.TANH, po-products, 4 shfl
// rounds, STS 8 partials, __syncthreads, 4 broadcast LDS.128 + tree.
// r exported fp16 (2x cvt.f16x2 + STG.64) in the shuffle shadow.
//
// Project (REWORKED): persistent warps, weights in REGISTERS. R15 ncu showed
// L1 76% / DRAM 33%: the 6 LDS.128 weight reads per warp-row (24 wavefronts)
// tripled the 2 LDG.128 (8 wavefronts). Each warp now loads its 12 weight
// float4s once and streams 8 rows: per row only 2 coalesced LDG.128 + FMAs
// + 15 shfl. No smem, no __syncthreads.

#define TSTEPS 1000
#define BATCH  64
#define HID    512
#define OUTDIM 3
#define NTHR   128          // 4 warps
#define UPT    4            // hidden units per thread
#define NROWS  (TSTEPS * BATCH)
#define RPW    8            // rows per warp in project

// fp16 r scratch: [row][512 halves] as uint2 (4 halves) -> 65.5 MB
__device__ uint2 g_rh[NROWS * (HID / 4)];

__global__ __launch_bounds__(NTHR, 1)
void rate_rnn_scan_kernel(const float* __restrict__ x,
                          const float* __restrict__ Win,
                          const float* __restrict__ pin,
                          const float* __restrict__ pout,
                          const float* __restrict__ l)
{
    const int b    = blockIdx.x;
    const int tid  = threadIdx.x;
    const int lane = tid & 31;
    const int wid  = tid >> 5;
    const int half = lane >> 4;            // 0: lanes 0-15, 1: lanes 16-31
    const int slot = wid * 2 + half;       // 8 partial slots
    const bool writer = ((lane & 15) == 0);

    __shared__ float4 xs[TSTEPS + 1];             // staged input (+1 pad)
    __shared__ __align__(16) float2 sp[2][8];     // double-buffered s partials

    const float4* x4 = reinterpret_cast<const float4*>(x);  // x: [T,B,4,1]
    for (int t = tid; t < TSTEPS; t += NTHR)
        xs[t] = x4[t * BATCH + b];
    if (tid == 0) xs[TSTEPS] = make_float4(0.f, 0.f, 0.f, 0.f);

    const float lm = 0.90483741803595952735f;   // exp(-dt/taum) = exp(-0.1)
    const float om = 1.0f - lm;
    const float l0 = l[0], l1 = l[1];

    float4 wi[UPT];
    float  pi0[UPT], pi1[UPT], po0[UPT], po1[UPT];
    float  acc[UPT], M[UPT];
#pragma unroll
    for (int k = 0; k < UPT; ++k) {
        int h = tid * UPT + k;
        float4 w = reinterpret_cast<const float4*>(Win)[h];
        wi[k] = make_float4(w.x * om, w.y * om, w.z * om, w.w * om);
        pi0[k] = pin[h * 2 + 0] * l0 * om;
        pi1[k] = pin[h * 2 + 1] * l1 * om;
        po0[k] = pout[h * 2 + 0];
        po1[k] = pout[h * 2 + 1];
        M[k]   = 0.0f;
    }

    float s0 = 0.f, s1 = 0.f;       // pout^T tanh(mem_{t-1}); zero at t=0
    int buf = 0;
    uint2* rrow = g_rh + (size_t)b * (HID / 4) + tid;

    __syncthreads();   // xs staged

    {   // prologue: acc for t=0 (M = 0)
        float4 x0 = xs[0];
#pragma unroll
        for (int k = 0; k < UPT; ++k)
            acc[k] = fmaf(wi[k].w, x0.w, fmaf(wi[k].z, x0.z,
                     fmaf(wi[k].y, x0.y, wi[k].x * x0.x)));
    }

    for (int t = 0; t < TSTEPS; ++t) {
        // ---- critical chain: s -> M -> tanh (single MUFU.TANH) ----
        float r[UPT];
#pragma unroll
        for (int k = 0; k < UPT; ++k) {
            float m = fmaf(pi1[k], s1, fmaf(pi0[k], s0, acc[k]));
            M[k] = m;
            asm("tanh.approx.f32 %0, %1;" : "=f"(r[k]) : "f"(m));
        }

        // s-products + 4 shuffle rounds (only pre-barrier reduction work)
        float v = fmaf(po0[1], r[1], po0[0] * r[0]) + fmaf(po0[3], r[3], po0[2] * r[2]);
        float u = fmaf(po1[1], r[1], po1[0] * r[0]) + fmaf(po1[3], r[3], po1[2] * r[2]);
#pragma unroll
        for (int off = 1; off <= 8; off <<= 1) {
            v += __shfl_down_sync(0xffffffffu, v, off);
            u += __shfl_down_sync(0xffffffffu, u, off);
        }

        // shuffle-shadow work: fp16 r export + next-step acc
        {
            union { __half2 h[2]; uint2 q; } pk;
            pk.h[0] = __floats2half2_rn(r[0], r[1]);
            pk.h[1] = __floats2half2_rn(r[2], r[3]);
            rrow[(size_t)t * (BATCH * (HID / 4))] = pk.q;
        }
        float4 xtn = xs[t + 1];
#pragma unroll
        for (int k = 0; k < UPT; ++k) {
            float iin = fmaf(wi[k].w, xtn.w, fmaf(wi[k].z, xtn.z,
                        fmaf(wi[k].y, xtn.y, wi[k].x * xtn.x)));
            acc[k] = fmaf(lm, M[k], iin);
        }

        if (writer) sp[buf][slot] = make_float2(v, u);
        __syncthreads();   // 4-warp barrier

        // 8 s-partials as 4 broadcast float4 loads + depth-3 tree
        const float4* q = reinterpret_cast<const float4*>(sp[buf]);
        float4 q0 = q[0], q1 = q[1], q2 = q[2], q3 = q[3];
        s0 = ((q0.x + q0.z) + (q1.x + q1.z)) + ((q2.x + q2.z) + (q3.x + q3.z));
        s1 = ((q0.y + q0.w) + (q1.y + q1.w)) + ((q2.y + q2.w) + (q3.y + q3.w));
        buf ^= 1;
    }
}

// y[row,o] = sum_h Wout[o,h]*r[row,h]; fp16 r. Persistent warps: each warp
// streams RPW consecutive rows with its weight slice held in registers.
// Per row per lane: 2 coalesced LDG.128 + 8 cvt + 30 FMA; 15 shfl per warp.
__global__ __launch_bounds__(256, 4)
void project_y_kernel(const float* __restrict__ Wout, float* __restrict__ out)
{
    const int tid  = threadIdx.x;
    const int lane = tid & 31;
    const int wrp  = tid >> 5;

    // Lane's weight slice: for j in {0,1}, halves [8m, 8m+8) at m = j*32+lane.
    const float4* w4 = reinterpret_cast<const float4*>(Wout);
    float4 wa[2][OUTDIM], wc[2][OUTDIM];
#pragma unroll
    for (int j = 0; j < 2; ++j) {
        int m = j * 32 + lane;
#pragma unroll
        for (int o = 0; o < OUTDIM; ++o) {
            wa[j][o] = w4[o * (HID / 4) + 2 * m];       // halves [8m, 8m+4)
            wc[j][o] = w4[o * (HID / 4) + 2 * m + 1];   // halves [8m+4, 8m+8)
        }
    }

    int row0 = (blockIdx.x * 8 + wrp) * RPW;            // warp's first row

#pragma unroll
    for (int rr = 0; rr < RPW; ++rr) {
        int row = row0 + rr;
        const uint4* rp = reinterpret_cast<const uint4*>(g_rh)
                        + (size_t)row * (HID / 8);

        float y0 = 0.f, y1 = 0.f, y2 = 0.f;
#pragma unroll
        for (int j = 0; j < 2; ++j) {
            uint4 rv = rp[j * 32 + lane];               // coalesced LDG.128
            const __half2* hp = reinterpret_cast<const __half2*>(&rv);
            float2 f0 = __half22float2(hp[0]);
            float2 f1 = __half22float2(hp[1]);
            float2 f2 = __half22float2(hp[2]);
            float2 f3 = __half22float2(hp[3]);
#pragma unroll
            for (int o = 0; o < OUTDIM; ++o) {
                float4 a = wa[j][o], c = wc[j][o];
                float acc =            fmaf(a.x, f0.x, a.y * f0.y);
                acc = fmaf(a.z, f1.x, fmaf(a.w, f1.y, acc));
                acc = fmaf(c.x, f2.x, fmaf(c.y, f2.y, acc));
                acc = fmaf(c.z, f3.x, fmaf(c.w, f3.y, acc));
                if (o == 0) y0 += acc; else if (o == 1) y1 += acc; else y2 += acc;
            }
        }
#pragma unroll
        for (int off = 16; off >= 1; off >>= 1) {
            y0 += __shfl_xor_sync(0xffffffffu, y0, off);
            y1 += __shfl_xor_sync(0xffffffffu, y1, off);
            y2 += __shfl_xor_sync(0xffffffffu, y2, off);
        }
        if (lane == 0) {
            out[row * OUTDIM + 0] = y0;   // y: [T,B,OUT,1], row = t*B + b
            out[row * OUTDIM + 1] = y1;
            out[row * OUTDIM + 2] = y2;
        }
    }
}

extern "C" void kernel_launch(void* const* d_in, const int* in_sizes, int n_in,
                              void* d_out, int out_size)
{
    const float* x    = (const float*)d_in[0];  // [1000,64,4,1]
    const float* Win  = (const float*)d_in[1];  // [512,4]
    const float* Wout = (const float*)d_in[2];  // [3,512]
    const float* pin  = (const float*)d_in[3];  // [512,2]
    const float* pout = (const float*)d_in[4];  // [512,2]
    const float* l    = (const float*)d_in[5];  // [2]

    rate_rnn_scan_kernel<<<BATCH, NTHR>>>(x, Win, pin, pout, l);
    project_y_kernel<<<NROWS / (8 * RPW), 256>>>(Wout, (float*)d_out);
}